// round 14
// baseline (speedup 1.0000x reference)
#include <cuda_runtime.h>
#include <math.h>
#include <stdint.h>

typedef unsigned long long ull;

// Problem constants
#define Bq 256
#define Tt 64
#define Ee 300
#define EeP 304
#define Hh 512
#define H2 1024
#define H4 2048
#define DAa 350
#define DAaP 384
#define Rr 16
#define Ss 64
#define Aa 16
#define NRr 3

// ---------------- scratch (device globals) ----------------------------------
__device__ float g_x[Tt * Bq * EeP];
__device__ float g_pre_f[Tt * Bq * H4];
__device__ float g_pre_b[Tt * Bq * H4];
__device__ float g_l0[Tt * Bq * H2];
__device__ float g_l1[Tt * Bq * H2];
__device__ float g_hf2[2][Bq * Hh];
__device__ float g_hb2[2][Bq * Hh];
__device__ float g_cf[Bq * Hh], g_cb[Bq * Hh];
__device__ float g_hbar[Tt * Bq * DAaP];       // padded stride 384
__device__ float g_alphas[Tt * Bq * Rr];
__device__ float g_votes[Bq * Rr * Ss * Aa];
__device__ float g_ws1p[DAaP * H2];            // ws1 padded to 384 rows
// packed weights: row r = 32*(h>>3) + 8*gate + (h&7)  (fp32)
__device__ float g_wih0f[H4 * EeP], g_wih0b[H4 * EeP];
__device__ float g_wih1f[H4 * H2],  g_wih1b[H4 * H2];
__device__ float g_whh0f[H4 * Hh],  g_whh0b[H4 * Hh];
__device__ float g_whh1f[H4 * Hh],  g_whh1b[H4 * Hh];
__device__ float g_b0f[H4], g_b0b[H4], g_b1f[H4], g_b1b[H4];

__device__ __forceinline__ float sigf(float x) { return 1.0f / (1.0f + expf(-x)); }

// ---- tf32 helpers -----------------------------------------------------------
__device__ __forceinline__ void tf32split(float x, uint32_t& hi, uint32_t& lo) {
    asm("cvt.rna.tf32.f32 %0, %1;" : "=r"(hi) : "f"(x));
    float r = x - __uint_as_float(hi);
    asm("cvt.rna.tf32.f32 %0, %1;" : "=r"(lo) : "f"(r));
}
__device__ __forceinline__ void mma_tf32(float* c,
                                         uint32_t a0, uint32_t a1, uint32_t a2, uint32_t a3,
                                         uint32_t b0, uint32_t b1) {
    asm("mma.sync.aligned.m16n8k8.row.col.f32.tf32.tf32.f32 "
        "{%0,%1,%2,%3}, {%4,%5,%6,%7}, {%8,%9}, {%0,%1,%2,%3};"
        : "+f"(c[0]), "+f"(c[1]), "+f"(c[2]), "+f"(c[3])
        : "r"(a0), "r"(a1), "r"(a2), "r"(a3), "r"(b0), "r"(b1));
}

__device__ __forceinline__ ull pack2(float lo, float hi) {
    ull r; asm("mov.b64 %0, {%1,%2};" : "=l"(r) : "f"(lo), "f"(hi)); return r;
}
__device__ __forceinline__ void unpack2(ull v, float& lo, float& hi) {
    asm("mov.b64 {%0,%1}, %2;" : "=f"(lo), "=f"(hi) : "l"(v));
}
__device__ __forceinline__ ull ffma2(ull a, ull b, ull c) {
    ull d; asm("fma.rn.f32x2 %0, %1, %2, %3;" : "=l"(d) : "l"(a), "l"(b), "l"(c)); return d;
}

// ---------------- embedding lookup, padded to EeP ---------------------------
__global__ void embed_kernel(const int* __restrict__ tokens,
                             const float* __restrict__ emb) {
    size_t n = (size_t)Tt * Bq * EeP;
    for (size_t i = (size_t)blockIdx.x * blockDim.x + threadIdx.x; i < n;
         i += (size_t)gridDim.x * blockDim.x) {
        int e = (int)(i % EeP);
        size_t tb = i / EeP;
        int b = (int)(tb % Bq);
        int t = (int)(tb / Bq);
        if (e < Ee) {
            int tok = tokens[b * Tt + t];
            g_x[i] = emb[(size_t)tok * Ee + e];
        } else {
            g_x[i] = 0.0f;
        }
    }
}

// ---------------- fused weight+bias repack (single launch, fp32) ------------
// permutation: out row r -> (h,gate): hgrp=r>>5, gate=(r&31)>>3, h=hgrp*8+(r&7)
struct PackArgs {
    const float* wsrc[8]; float* wdst[8]; int K[8]; int Kp[8];
    const float* bsrc[4]; float* bdst[4];
};
__global__ void pack_all(PackArgs pa) {
    int off[9];
    off[0] = 0;
#pragma unroll
    for (int s = 0; s < 8; s++) off[s + 1] = off[s] + H4 * pa.Kp[s];
    int totalW = off[8];
    int total = totalW + 4 * H4;
    for (int idx = blockIdx.x * blockDim.x + threadIdx.x; idx < total;
         idx += gridDim.x * blockDim.x) {
        if (idx < totalW) {
            int s = 0;
#pragma unroll
            for (int q = 0; q < 8; q++) if (idx >= off[q + 1]) s = q + 1;
            int li = idx - off[s];
            int Kp = pa.Kp[s], K = pa.K[s];
            int r = li / Kp, k = li - r * Kp;
            int gate = (r & 31) >> 3;
            int h = (r >> 5) * 8 + (r & 7);
            pa.wdst[s][li] = (k < K) ? pa.wsrc[s][(size_t)(gate * Hh + h) * K + k] : 0.0f;
        } else {
            int li = idx - totalW;
            int s = li / H4, j = li - s * H4;
            int gate = (j & 31) >> 3;
            int h = (j >> 5) * 8 + (j & 7);
            pa.bdst[s][j] = pa.bsrc[s][gate * Hh + h];
        }
    }
}

// ---------------- ws1 pad: 350x1024 -> 384x1024 (zeros) ----------------------
__global__ void pack_ws1b(const float* __restrict__ ws1) {
    int total = DAaP * H2;
    for (int i = blockIdx.x * blockDim.x + threadIdx.x; i < total;
         i += gridDim.x * blockDim.x) {
        int r = i / H2, k = i - r * H2;
        g_ws1p[i] = (r < DAa) ? ws1[(size_t)r * H2 + k] : 0.0f;
    }
}

// ---------------- tf32 tensor-core GEMM (3xTF32, inline split) ---------------
// C = A @ B^T ; M,N multiples of 128; K multiple of 16. fwd+bwd via blockIdx.z.
// Double-buffered smem (one __syncthreads per k16 tile). act=1 -> tanh.
__global__ __launch_bounds__(256)
void gemm_tf32_2(const float* __restrict__ A,
                 const float* __restrict__ Bf, const float* __restrict__ Bb,
                 float* __restrict__ Cf, float* __restrict__ Cb,
                 int M, int N, int K, int act) {
    extern __shared__ uint32_t sm[];
    const float* Bm = blockIdx.z ? Bb : Bf;
    float* C = blockIdx.z ? Cb : Cf;

    const int tid = threadIdx.x;
    const int lane = tid & 31, warp = tid >> 5;
    const int wm = warp >> 2, wn = warp & 3;
    const int g = lane >> 2, t4 = lane & 3;
    const int m0 = blockIdx.y * 128, n0 = blockIdx.x * 128;
    const int lrow = tid >> 1;
    const int lhalf = (tid & 1) * 8;

    float acc[4][4][4];
#pragma unroll
    for (int i = 0; i < 4; i++)
#pragma unroll
        for (int j = 0; j < 4; j++)
#pragma unroll
            for (int q = 0; q < 4; q++) acc[i][j][q] = 0.0f;

    const float* Aptr = A + (size_t)(m0 + lrow) * K + lhalf;
    const float* Bptr = Bm + (size_t)(n0 + lrow) * K + lhalf;
    float4 pa0 = *(const float4*)Aptr;
    float4 pa1 = *(const float4*)(Aptr + 4);
    float4 pb0 = *(const float4*)Bptr;
    float4 pb1 = *(const float4*)(Bptr + 4);

    for (int k0 = 0; k0 < K; k0 += 16) {
        uint32_t* S = sm + ((k0 >> 4) & 1) * 10240;
        uint32_t* Ahi = S;
        uint32_t* Alo = S + 2560;
        uint32_t* Bhi = S + 5120;
        uint32_t* Blo = S + 7680;
        {
            uint4 h, l;
            tf32split(pa0.x, h.x, l.x); tf32split(pa0.y, h.y, l.y);
            tf32split(pa0.z, h.z, l.z); tf32split(pa0.w, h.w, l.w);
            *(uint4*)&Ahi[lrow * 20 + lhalf] = h; *(uint4*)&Alo[lrow * 20 + lhalf] = l;
            tf32split(pa1.x, h.x, l.x); tf32split(pa1.y, h.y, l.y);
            tf32split(pa1.z, h.z, l.z); tf32split(pa1.w, h.w, l.w);
            *(uint4*)&Ahi[lrow * 20 + lhalf + 4] = h; *(uint4*)&Alo[lrow * 20 + lhalf + 4] = l;
            tf32split(pb0.x, h.x, l.x); tf32split(pb0.y, h.y, l.y);
            tf32split(pb0.z, h.z, l.z); tf32split(pb0.w, h.w, l.w);
            *(uint4*)&Bhi[lrow * 20 + lhalf] = h; *(uint4*)&Blo[lrow * 20 + lhalf] = l;
            tf32split(pb1.x, h.x, l.x); tf32split(pb1.y, h.y, l.y);
            tf32split(pb1.z, h.z, l.z); tf32split(pb1.w, h.w, l.w);
            *(uint4*)&Bhi[lrow * 20 + lhalf + 4] = h; *(uint4*)&Blo[lrow * 20 + lhalf + 4] = l;
        }
        __syncthreads();
        int k1 = k0 + 16;
        if (k1 < K) {
            pa0 = *(const float4*)(Aptr + k1);
            pa1 = *(const float4*)(Aptr + k1 + 4);
            pb0 = *(const float4*)(Bptr + k1);
            pb1 = *(const float4*)(Bptr + k1 + 4);
        }
#pragma unroll
        for (int k8 = 0; k8 < 16; k8 += 8) {
            uint32_t bh[4][2], bl[4][2];
#pragma unroll
            for (int tn = 0; tn < 4; tn++) {
                int nr = wn * 32 + tn * 8 + g;
                bh[tn][0] = Bhi[nr * 20 + k8 + t4]; bh[tn][1] = Bhi[nr * 20 + k8 + t4 + 4];
                bl[tn][0] = Blo[nr * 20 + k8 + t4]; bl[tn][1] = Blo[nr * 20 + k8 + t4 + 4];
            }
#pragma unroll
            for (int tm = 0; tm < 4; tm++) {
                int mr = wm * 64 + tm * 16 + g;
                uint32_t ah0 = Ahi[mr * 20 + k8 + t4],       ah1 = Ahi[(mr + 8) * 20 + k8 + t4];
                uint32_t ah2 = Ahi[mr * 20 + k8 + t4 + 4],   ah3 = Ahi[(mr + 8) * 20 + k8 + t4 + 4];
                uint32_t al0 = Alo[mr * 20 + k8 + t4],       al1 = Alo[(mr + 8) * 20 + k8 + t4];
                uint32_t al2 = Alo[mr * 20 + k8 + t4 + 4],   al3 = Alo[(mr + 8) * 20 + k8 + t4 + 4];
#pragma unroll
                for (int tn = 0; tn < 4; tn++) {
                    mma_tf32(acc[tm][tn], ah0, ah1, ah2, ah3, bh[tn][0], bh[tn][1]);
                    mma_tf32(acc[tm][tn], ah0, ah1, ah2, ah3, bl[tn][0], bl[tn][1]);
                    mma_tf32(acc[tm][tn], al0, al1, al2, al3, bh[tn][0], bh[tn][1]);
                }
            }
        }
    }
#pragma unroll
    for (int tm = 0; tm < 4; tm++) {
#pragma unroll
        for (int tn = 0; tn < 4; tn++) {
            int m = m0 + wm * 64 + tm * 16 + g;
            int n = n0 + wn * 32 + tn * 8 + 2 * t4;
            float v0 = acc[tm][tn][0], v1 = acc[tm][tn][1];
            float v2 = acc[tm][tn][2], v3 = acc[tm][tn][3];
            if (act) { v0 = tanhf(v0); v1 = tanhf(v1); v2 = tanhf(v2); v3 = tanhf(v3); }
            *(float2*)&C[(size_t)m * N + n] = make_float2(v0, v1);
            *(float2*)&C[(size_t)(m + 8) * N + n] = make_float2(v2, v3);
        }
    }
}

// ---------------- fused mma LSTM recurrence step ------------------------------
// z = h_in @ Whh_p^T (3xTF32, K=512); epilogue: +pre +bias -> gates -> c,h.
// Permutation r = 32*(h>>3)+8*gate+(h&7): each thread owns all 4 gates of 2 h.
__global__ __launch_bounds__(256)
void recur_mma(int step,
               const float* __restrict__ Wpf, const float* __restrict__ Wpb,
               const float* __restrict__ bpf, const float* __restrict__ bpb,
               const float* __restrict__ pre_f, const float* __restrict__ pre_b,
               const float* __restrict__ hinf, const float* __restrict__ hinb,
               float* __restrict__ houtf, float* __restrict__ houtb,
               float* __restrict__ out) {
    extern __shared__ uint32_t sm[];
    const int dir = blockIdx.z;
    const float* Bm  = dir ? Wpb : Wpf;
    const float* bia = dir ? bpb : bpf;
    const float* pre = dir ? pre_b : pre_f;
    const float* A   = dir ? hinb : hinf;
    float* hout = dir ? houtb : houtf;
    float* cs   = dir ? g_cb : g_cf;
    const int tc = dir ? (Tt - 1 - step) : step;

    const int tid = threadIdx.x;
    const int lane = tid & 31, warp = tid >> 5;
    const int wm = warp >> 2, wn = warp & 3;
    const int g = lane >> 2, t4 = lane & 3;
    const int m0 = blockIdx.y * 128, n0 = blockIdx.x * 128;
    const int lrow = tid >> 1;
    const int lhalf = (tid & 1) * 8;

    float acc[4][4][4];
#pragma unroll
    for (int i = 0; i < 4; i++)
#pragma unroll
        for (int j = 0; j < 4; j++)
#pragma unroll
            for (int q = 0; q < 4; q++) acc[i][j][q] = 0.0f;

    const float* Aptr = A + (size_t)(m0 + lrow) * Hh + lhalf;
    const float* Bptr = Bm + (size_t)(n0 + lrow) * Hh + lhalf;
    float4 pa0 = *(const float4*)Aptr;
    float4 pa1 = *(const float4*)(Aptr + 4);
    float4 pb0 = *(const float4*)Bptr;
    float4 pb1 = *(const float4*)(Bptr + 4);

    for (int k0 = 0; k0 < Hh; k0 += 16) {
        uint32_t* S = sm + ((k0 >> 4) & 1) * 10240;
        uint32_t* Ahi = S;
        uint32_t* Alo = S + 2560;
        uint32_t* Bhi = S + 5120;
        uint32_t* Blo = S + 7680;
        {
            uint4 h, l;
            tf32split(pa0.x, h.x, l.x); tf32split(pa0.y, h.y, l.y);
            tf32split(pa0.z, h.z, l.z); tf32split(pa0.w, h.w, l.w);
            *(uint4*)&Ahi[lrow * 20 + lhalf] = h; *(uint4*)&Alo[lrow * 20 + lhalf] = l;
            tf32split(pa1.x, h.x, l.x); tf32split(pa1.y, h.y, l.y);
            tf32split(pa1.z, h.z, l.z); tf32split(pa1.w, h.w, l.w);
            *(uint4*)&Ahi[lrow * 20 + lhalf + 4] = h; *(uint4*)&Alo[lrow * 20 + lhalf + 4] = l;
            tf32split(pb0.x, h.x, l.x); tf32split(pb0.y, h.y, l.y);
            tf32split(pb0.z, h.z, l.z); tf32split(pb0.w, h.w, l.w);
            *(uint4*)&Bhi[lrow * 20 + lhalf] = h; *(uint4*)&Blo[lrow * 20 + lhalf] = l;
            tf32split(pb1.x, h.x, l.x); tf32split(pb1.y, h.y, l.y);
            tf32split(pb1.z, h.z, l.z); tf32split(pb1.w, h.w, l.w);
            *(uint4*)&Bhi[lrow * 20 + lhalf + 4] = h; *(uint4*)&Blo[lrow * 20 + lhalf + 4] = l;
        }
        __syncthreads();
        int k1 = k0 + 16;
        if (k1 < Hh) {
            pa0 = *(const float4*)(Aptr + k1);
            pa1 = *(const float4*)(Aptr + k1 + 4);
            pb0 = *(const float4*)(Bptr + k1);
            pb1 = *(const float4*)(Bptr + k1 + 4);
        }
#pragma unroll
        for (int k8 = 0; k8 < 16; k8 += 8) {
            uint32_t bh[4][2], bl[4][2];
#pragma unroll
            for (int tn = 0; tn < 4; tn++) {
                int nr = wn * 32 + tn * 8 + g;
                bh[tn][0] = Bhi[nr * 20 + k8 + t4]; bh[tn][1] = Bhi[nr * 20 + k8 + t4 + 4];
                bl[tn][0] = Blo[nr * 20 + k8 + t4]; bl[tn][1] = Blo[nr * 20 + k8 + t4 + 4];
            }
#pragma unroll
            for (int tm = 0; tm < 4; tm++) {
                int mr = wm * 64 + tm * 16 + g;
                uint32_t ah0 = Ahi[mr * 20 + k8 + t4],       ah1 = Ahi[(mr + 8) * 20 + k8 + t4];
                uint32_t ah2 = Ahi[mr * 20 + k8 + t4 + 4],   ah3 = Ahi[(mr + 8) * 20 + k8 + t4 + 4];
                uint32_t al0 = Alo[mr * 20 + k8 + t4],       al1 = Alo[(mr + 8) * 20 + k8 + t4];
                uint32_t al2 = Alo[mr * 20 + k8 + t4 + 4],   al3 = Alo[(mr + 8) * 20 + k8 + t4 + 4];
#pragma unroll
                for (int tn = 0; tn < 4; tn++) {
                    mma_tf32(acc[tm][tn], ah0, ah1, ah2, ah3, bh[tn][0], bh[tn][1]);
                    mma_tf32(acc[tm][tn], ah0, ah1, ah2, ah3, bl[tn][0], bl[tn][1]);
                    mma_tf32(acc[tm][tn], al0, al1, al2, al3, bh[tn][0], bh[tn][1]);
                }
            }
        }
    }

    // ---- fused LSTM epilogue: gate=tn, h pair = (hv0, hv0+1) ----------------
    const int colbase = n0 + wn * 32;          // 32-col h-group
    const int hv0 = (colbase >> 5) * 8 + 2 * t4;
    float bi[4][2];
#pragma unroll
    for (int gt = 0; gt < 4; gt++) {
        bi[gt][0] = bia[colbase + 8 * gt + 2 * t4];
        bi[gt][1] = bia[colbase + 8 * gt + 2 * t4 + 1];
    }
#pragma unroll
    for (int tm = 0; tm < 4; tm++) {
        int bb = m0 + wm * 64 + tm * 16 + g;
#pragma unroll
        for (int rs = 0; rs < 2; rs++) {
            int b = bb + rs * 8;
            const float* prow = pre + ((size_t)tc * Bq + b) * H4 + colbase + 2 * t4;
#pragma unroll
            for (int hs = 0; hs < 2; hs++) {
                int q = 2 * rs + hs;
                float zi = acc[tm][0][q] + prow[hs]      + bi[0][hs];
                float zf = acc[tm][1][q] + prow[8 + hs]  + bi[1][hs];
                float zg = acc[tm][2][q] + prow[16 + hs] + bi[2][hs];
                float zo = acc[tm][3][q] + prow[24 + hs] + bi[3][hs];
                int h = hv0 + hs;
                float c = cs[b * Hh + h];
                c = sigf(zf) * c + sigf(zi) * tanhf(zg);
                float hn = sigf(zo) * tanhf(c);
                cs[b * Hh + h] = c;
                hout[b * Hh + h] = hn;
                out[((size_t)tc * Bq + b) * H2 + dir * Hh + h] = hn;
            }
        }
    }
}

// ---------------- zero LSTM states ------------------------------------------
__global__ void zero_states_kernel() {
    int i = blockIdx.x * blockDim.x + threadIdx.x;
    if (i < Bq * Hh) {
        g_hf2[0][i] = 0.0f; g_hf2[1][i] = 0.0f;
        g_hb2[0][i] = 0.0f; g_hb2[1][i] = 0.0f;
        g_cf[i] = 0.0f; g_cb[i] = 0.0f;
    }
}

// ---------------- alphas: [tb][r] = dot(hbar[tb], ws2[r]) -------------------
__global__ void alphas_kernel(const float* __restrict__ hbar,
                              const float* __restrict__ ws2,
                              float* __restrict__ alph) {
    __shared__ float w[Rr * 353];
    int tid = threadIdx.x;  // 128
    for (int i = tid; i < Rr * DAa; i += 128) {
        int r = i / DAa, k = i - r * DAa;
        w[r * 353 + k] = ws2[i];
    }
    __syncthreads();
    int row = blockIdx.x * 8 + (tid >> 4);
    int r = tid & 15;
    const float* hb = hbar + (size_t)row * DAaP;
    float acc = 0.0f;
    for (int k = 0; k < DAa; k++) acc += hb[k] * w[r * 353 + k];
    alph[(size_t)row * Rr + r] = acc;
}

// ---------------- sent: sent[b,r,e] = sum_t alphas[t,b,r] * l1[t,b,e] -------
__global__ void sent_kernel(const float* __restrict__ alphas,
                            const float* __restrict__ l1,
                            float* __restrict__ outSent) {
    int b = blockIdx.x;
    __shared__ float al[Tt * Rr];
    int tid = threadIdx.x;
    for (int i = tid; i < Tt * Rr; i += 256) {
        int t = i / Rr, r = i % Rr;
        al[i] = alphas[(size_t)(t * Bq + b) * Rr + r];
    }
    __syncthreads();
    for (int e = tid; e < H2; e += 256) {
        float acc[Rr];
#pragma unroll
        for (int r = 0; r < Rr; r++) acc[r] = 0.0f;
        for (int t = 0; t < Tt; t++) {
            float v = l1[(size_t)(t * Bq + b) * H2 + e];
#pragma unroll
            for (int r = 0; r < Rr; r++) acc[r] += al[t * Rr + r] * v;
        }
#pragma unroll
        for (int r = 0; r < Rr; r++)
            outSent[(size_t)(b * Rr + r) * H2 + e] = acc[r];
    }
}

// ---------------- votes: per-r NN GEMM, f32x2, gemm128 pattern (R12 WIN) -----
__global__ __launch_bounds__(256)
void votes_f32x2(const float* __restrict__ sent, const float* __restrict__ capsW,
                 float* __restrict__ votes) {
    const int rr = blockIdx.z;
    const float* Bp = capsW + (size_t)rr * H2 * (Ss * Aa);
    __shared__ __align__(16) float As[16][132];
    __shared__ __align__(16) float Bs[16][132];
    const int tid = threadIdx.x;
    const int tx = tid & 15, ty = tid >> 4;
    const int m0 = blockIdx.y * 128, n0 = blockIdx.x * 128;
    const int lr = tid >> 2;
    const int lk = (tid & 3) << 2;

    ull acc[8][4];
#pragma unroll
    for (int i = 0; i < 8; i++)
#pragma unroll
        for (int j = 0; j < 4; j++) acc[i][j] = 0ULL;

    float4 pa0 = *(const float4*)&sent[((size_t)(m0 + lr) * Rr + rr) * H2 + lk];
    float4 pa1 = *(const float4*)&sent[((size_t)(m0 + lr + 64) * Rr + rr) * H2 + lk];
    const int kr = tid >> 5;
    const int nc = (tid & 31) << 2;
    float4 pb0 = *(const float4*)&Bp[(size_t)(kr)     * (Ss * Aa) + n0 + nc];
    float4 pb1 = *(const float4*)&Bp[(size_t)(kr + 8) * (Ss * Aa) + n0 + nc];

    for (int k0 = 0; k0 < H2; k0 += 16) {
        __syncthreads();
        As[lk + 0][lr] = pa0.x; As[lk + 1][lr] = pa0.y;
        As[lk + 2][lr] = pa0.z; As[lk + 3][lr] = pa0.w;
        As[lk + 0][lr + 64] = pa1.x; As[lk + 1][lr + 64] = pa1.y;
        As[lk + 2][lr + 64] = pa1.z; As[lk + 3][lr + 64] = pa1.w;
        *(float4*)&Bs[kr][nc]     = pb0;
        *(float4*)&Bs[kr + 8][nc] = pb1;
        __syncthreads();
        int k1 = k0 + 16;
        if (k1 < H2) {
            pa0 = *(const float4*)&sent[((size_t)(m0 + lr) * Rr + rr) * H2 + k1 + lk];
            pa1 = *(const float4*)&sent[((size_t)(m0 + lr + 64) * Rr + rr) * H2 + k1 + lk];
            pb0 = *(const float4*)&Bp[(size_t)(k1 + kr)     * (Ss * Aa) + n0 + nc];
            pb1 = *(const float4*)&Bp[(size_t)(k1 + kr + 8) * (Ss * Aa) + n0 + nc];
        }
#pragma unroll
        for (int k = 0; k < 16; k++) {
            ull b2[4];
            const ull* bp = (const ull*)&Bs[k][tx << 3];
            b2[0] = bp[0]; b2[1] = bp[1]; b2[2] = bp[2]; b2[3] = bp[3];
#pragma unroll
            for (int i = 0; i < 8; i++) {
                float a = As[k][(ty << 3) + i];
                ull ad = pack2(a, a);
#pragma unroll
                for (int j = 0; j < 4; j++) acc[i][j] = ffma2(ad, b2[j], acc[i][j]);
            }
        }
    }
#pragma unroll
    for (int i = 0; i < 8; i++) {
        int m = m0 + (ty << 3) + i;
#pragma unroll
        for (int j = 0; j < 4; j++) {
            float lo, hi;
            unpack2(acc[i][j], lo, hi);
            int n = n0 + (tx << 3) + 2 * j;
            votes[((size_t)m * Rr + rr) * (Ss * Aa) + n]     = lo;
            votes[((size_t)m * Rr + rr) * (Ss * Aa) + n + 1] = hi;
        }
    }
}

// ---------------- dynamic routing (NR=3) + class logits ---------------------
__global__ void routing_kernel(const float* __restrict__ votes,
                               float* __restrict__ outCls) {
    int b = blockIdx.x, tid = threadIdx.x;
    __shared__ float logits[Rr * Ss];
    __shared__ float route[Rr * Ss];
    __shared__ float pre[Ss * Aa];
    __shared__ float scale[Ss];
    for (int i = tid; i < Rr * Ss; i += 256) logits[i] = 0.0f;
    const float* vb = votes + (size_t)b * Rr * Ss * Aa;
    for (int it = 0; it < NRr; it++) {
        __syncthreads();
        if (tid < Rr) {
            float mx = -1e30f;
            for (int s = 0; s < Ss; s++) mx = fmaxf(mx, logits[tid * Ss + s]);
            float sum = 0.0f;
            for (int s = 0; s < Ss; s++) {
                float e = expf(logits[tid * Ss + s] - mx);
                route[tid * Ss + s] = e;
                sum += e;
            }
            float inv = 1.0f / sum;
            for (int s = 0; s < Ss; s++) route[tid * Ss + s] *= inv;
        }
        __syncthreads();
        for (int i = tid; i < Ss * Aa; i += 256) {
            int s = i / Aa, a = i % Aa;
            float acc = 0.0f;
            for (int r = 0; r < Rr; r++)
                acc += route[r * Ss + s] * vb[(r * Ss + s) * Aa + a];
            pre[i] = acc;
        }
        __syncthreads();
        if (tid < Ss) {
            float n2 = 0.0f;
            for (int a = 0; a < Aa; a++) n2 += pre[tid * Aa + a] * pre[tid * Aa + a];
            float n = sqrtf(n2);
            scale[tid] = n / (0.5f + n2);
            if (it == NRr - 1) outCls[b * Ss + tid] = n2 / (0.5f + n2);
        }
        __syncthreads();
        if (it < NRr - 1) {
            for (int i = tid; i < Rr * Ss; i += 256) {
                int r = i / Ss, s = i % Ss;
                float acc = 0.0f;
                float sc = scale[s];
                for (int a = 0; a < Aa; a++)
                    acc += vb[(r * Ss + s) * Aa + a] * pre[s * Aa + a] * sc;
                logits[i] += acc;
            }
        }
    }
}

// ---------------- host launch ------------------------------------------------
static float* symf(const void* s) {
    void* p = nullptr;
    cudaGetSymbolAddress(&p, s);
    return (float*)p;
}

extern "C" void kernel_launch(void* const* d_in, const int* in_sizes, int n_in,
                              void* d_out, int out_size) {
    const int*   tokens  = (const int*)d_in[0];
    const float* emb     = (const float*)d_in[2];
    const float* Wih_l0f = (const float*)d_in[3];
    const float* Whh_l0f = (const float*)d_in[4];
    const float* b_l0f   = (const float*)d_in[5];
    const float* Wih_l0b = (const float*)d_in[6];
    const float* Whh_l0b = (const float*)d_in[7];
    const float* b_l0b   = (const float*)d_in[8];
    const float* Wih_l1f = (const float*)d_in[9];
    const float* Whh_l1f = (const float*)d_in[10];
    const float* b_l1f   = (const float*)d_in[11];
    const float* Wih_l1b = (const float*)d_in[12];
    const float* Whh_l1b = (const float*)d_in[13];
    const float* b_l1b   = (const float*)d_in[14];
    const float* ws1     = (const float*)d_in[15];
    const float* ws2     = (const float*)d_in[16];
    const float* capsW   = (const float*)d_in[17];
    float* out = (float*)d_out;

    float* x     = symf(g_x);
    float* pre_f = symf(g_pre_f);
    float* pre_b = symf(g_pre_b);
    float* l0    = symf(g_l0);
    float* l1    = symf(g_l1);
    float* hbar  = symf(g_hbar);
    float* alph  = symf(g_alphas);
    float* votes = symf(g_votes);
    float* ws1p  = symf(g_ws1p);
    float* wih0f = symf(g_wih0f); float* wih0b = symf(g_wih0b);
    float* wih1f = symf(g_wih1f); float* wih1b = symf(g_wih1b);
    float* whh0f = symf(g_whh0f); float* whh0b = symf(g_whh0b);
    float* whh1f = symf(g_whh1f); float* whh1b = symf(g_whh1b);
    float* bp0f  = symf(g_b0f);   float* bp0b  = symf(g_b0b);
    float* bp1f  = symf(g_b1f);   float* bp1b  = symf(g_b1b);
    float* hfbase = symf(g_hf2);
    float* hbbase = symf(g_hb2);
    float* hf0 = hfbase;              float* hf1 = hfbase + Bq * Hh;
    float* hb0 = hbbase;              float* hb1 = hbbase + Bq * Hh;

    const int MB = Tt * Bq;  // 16384
    const int GT_SMEM = 81920;  // 2-stage double buffer

    cudaFuncSetAttribute(gemm_tf32_2, cudaFuncAttributeMaxDynamicSharedMemorySize, GT_SMEM);
    cudaFuncSetAttribute(recur_mma, cudaFuncAttributeMaxDynamicSharedMemorySize, GT_SMEM);

    // 1. embedding (padded) + fused weight/bias repack (new permutation) + ws1 pad
    embed_kernel<<<4096, 256>>>(tokens, emb);
    {
        PackArgs pa;
        pa.wsrc[0] = Wih_l0f; pa.wdst[0] = wih0f; pa.K[0] = Ee;  pa.Kp[0] = EeP;
        pa.wsrc[1] = Wih_l0b; pa.wdst[1] = wih0b; pa.K[1] = Ee;  pa.Kp[1] = EeP;
        pa.wsrc[2] = Wih_l1f; pa.wdst[2] = wih1f; pa.K[2] = H2;  pa.Kp[2] = H2;
        pa.wsrc[3] = Wih_l1b; pa.wdst[3] = wih1b; pa.K[3] = H2;  pa.Kp[3] = H2;
        pa.wsrc[4] = Whh_l0f; pa.wdst[4] = whh0f; pa.K[4] = Hh;  pa.Kp[4] = Hh;
        pa.wsrc[5] = Whh_l0b; pa.wdst[5] = whh0b; pa.K[5] = Hh;  pa.Kp[5] = Hh;
        pa.wsrc[6] = Whh_l1f; pa.wdst[6] = whh1f; pa.K[6] = Hh;  pa.Kp[6] = Hh;
        pa.wsrc[7] = Whh_l1b; pa.wdst[7] = whh1b; pa.K[7] = Hh;  pa.Kp[7] = Hh;
        pa.bsrc[0] = b_l0f; pa.bdst[0] = bp0f;
        pa.bsrc[1] = b_l0b; pa.bdst[1] = bp0b;
        pa.bsrc[2] = b_l1f; pa.bdst[2] = bp1f;
        pa.bsrc[3] = b_l1b; pa.bdst[3] = bp1b;
        pack_all<<<4096, 256>>>(pa);
    }
    pack_ws1b<<<1536, 256>>>(ws1);

    dim3 gP(H4 / 128, MB / 128, 2);   // projections fwd+bwd in one launch
    dim3 gRM(H4 / 128, Bq / 128, 2);  // recurrence mma: 16 x 2 x 2 = 64 blocks

    // 2. layer0 input projections (tf32 tensor cores, 3xTF32, double-buffered)
    gemm_tf32_2<<<gP, 256, GT_SMEM>>>(x, wih0f, wih0b, pre_f, pre_b, MB, H4, EeP, 0);

    // 3. layer0 recurrence (fused mma steps, h ping-pong)
    zero_states_kernel<<<(Bq * Hh + 255) / 256, 256>>>();
    for (int t = 0; t < Tt; t++) {
        float* hinf = (t & 1) ? hf1 : hf0;  float* houtf = (t & 1) ? hf0 : hf1;
        float* hinb = (t & 1) ? hb1 : hb0;  float* houtb = (t & 1) ? hb0 : hb1;
        recur_mma<<<gRM, 256, GT_SMEM>>>(t, whh0f, whh0b, bp0f, bp0b, pre_f, pre_b,
                                         hinf, hinb, houtf, houtb, l0);
    }

    // 4. layer1 input projections
    gemm_tf32_2<<<gP, 256, GT_SMEM>>>(l0, wih1f, wih1b, pre_f, pre_b, MB, H4, H2, 0);

    // 5. layer1 recurrence
    zero_states_kernel<<<(Bq * Hh + 255) / 256, 256>>>();
    for (int t = 0; t < Tt; t++) {
        float* hinf = (t & 1) ? hf1 : hf0;  float* houtf = (t & 1) ? hf0 : hf1;
        float* hinb = (t & 1) ? hb1 : hb0;  float* houtb = (t & 1) ? hb0 : hb1;
        recur_mma<<<gRM, 256, GT_SMEM>>>(t, whh1f, whh1b, bp1f, bp1b, pre_f, pre_b,
                                         hinf, hinb, houtf, houtb, l1);
    }

    // 6. attention: hbar = tanh(l1 @ ws1p^T) via tf32 (N padded to 384)
    gemm_tf32_2<<<dim3(DAaP / 128, MB / 128, 1), 256, GT_SMEM>>>(
        l1, ws1p, ws1p, hbar, hbar, MB, DAaP, H2, 1);
    alphas_kernel<<<MB / 8, 128>>>(hbar, ws2, alph);

    // 7. sent -> d_out[0 : B*R*2H)
    sent_kernel<<<Bq, 256>>>(alph, l1, out);

    // 8. votes (f32x2, gemm128 pattern)
    votes_f32x2<<<dim3((Ss * Aa) / 128, Bq / 128, Rr), 256>>>(out, capsW, votes);

    // 9. routing -> class logits
    routing_kernel<<<Bq, 256>>>(votes, out + (size_t)Bq * Rr * H2);
}

// round 15
// speedup vs baseline: 1.5435x; 1.5435x over previous
#include <cuda_runtime.h>
#include <math.h>
#include <stdint.h>

typedef unsigned long long ull;

// Problem constants
#define Bq 256
#define Tt 64
#define Ee 300
#define EeP 304
#define Hh 512
#define H2 1024
#define H4 2048
#define DAa 350
#define DAaP 384
#define Rr 16
#define Ss 64
#define Aa 16
#define NRr 3

// ---------------- scratch (device globals) ----------------------------------
__device__ float g_x[Tt * Bq * EeP];
__device__ float g_pre_f[Tt * Bq * H4];
__device__ float g_pre_b[Tt * Bq * H4];
__device__ float g_l0[Tt * Bq * H2];
__device__ float g_l1[Tt * Bq * H2];
__device__ float g_hf2[2][Bq * Hh];
__device__ float g_hb2[2][Bq * Hh];
__device__ float g_cf[Bq * Hh], g_cb[Bq * Hh];
__device__ float g_hbar[Tt * Bq * DAaP];       // padded stride 384
__device__ float g_alphas[Tt * Bq * Rr];
__device__ float g_votes[Bq * Rr * Ss * Aa];
__device__ float g_ws1p[DAaP * H2];            // ws1 padded to 384 rows
// packed weights: row = h*4+g (fp32)  [R13 permutation]
__device__ float g_wih0f[H4 * EeP], g_wih0b[H4 * EeP];
__device__ float g_wih1f[H4 * H2],  g_wih1b[H4 * H2];
__device__ float g_whh0f[H4 * Hh],  g_whh0b[H4 * Hh];
__device__ float g_whh1f[H4 * Hh],  g_whh1b[H4 * Hh];
__device__ float g_b0f[H4], g_b0b[H4], g_b1f[H4], g_b1b[H4];

__device__ __forceinline__ float sigf(float x) { return 1.0f / (1.0f + expf(-x)); }

__device__ __forceinline__ ull pack2(float lo, float hi) {
    ull r; asm("mov.b64 %0, {%1,%2};" : "=l"(r) : "f"(lo), "f"(hi)); return r;
}
__device__ __forceinline__ void unpack2(ull v, float& lo, float& hi) {
    asm("mov.b64 {%0,%1}, %2;" : "=f"(lo), "=f"(hi) : "l"(v));
}
__device__ __forceinline__ ull ffma2(ull a, ull b, ull c) {
    ull d; asm("fma.rn.f32x2 %0, %1, %2, %3;" : "=l"(d) : "l"(a), "l"(b), "l"(c)); return d;
}

// ---- tf32 helpers -----------------------------------------------------------
__device__ __forceinline__ void tf32split(float x, uint32_t& hi, uint32_t& lo) {
    asm("cvt.rna.tf32.f32 %0, %1;" : "=r"(hi) : "f"(x));
    float r = x - __uint_as_float(hi);
    asm("cvt.rna.tf32.f32 %0, %1;" : "=r"(lo) : "f"(r));
}
__device__ __forceinline__ void mma_tf32(float* c,
                                         uint32_t a0, uint32_t a1, uint32_t a2, uint32_t a3,
                                         uint32_t b0, uint32_t b1) {
    asm("mma.sync.aligned.m16n8k8.row.col.f32.tf32.tf32.f32 "
        "{%0,%1,%2,%3}, {%4,%5,%6,%7}, {%8,%9}, {%0,%1,%2,%3};"
        : "+f"(c[0]), "+f"(c[1]), "+f"(c[2]), "+f"(c[3])
        : "r"(a0), "r"(a1), "r"(a2), "r"(a3), "r"(b0), "r"(b1));
}

// ---------------- embedding lookup, padded to EeP ---------------------------
__global__ void embed_kernel(const int* __restrict__ tokens,
                             const float* __restrict__ emb) {
    size_t n = (size_t)Tt * Bq * EeP;
    for (size_t i = (size_t)blockIdx.x * blockDim.x + threadIdx.x; i < n;
         i += (size_t)gridDim.x * blockDim.x) {
        int e = (int)(i % EeP);
        size_t tb = i / EeP;
        int b = (int)(tb % Bq);
        int t = (int)(tb / Bq);
        if (e < Ee) {
            int tok = tokens[b * Tt + t];
            g_x[i] = emb[(size_t)tok * Ee + e];
        } else {
            g_x[i] = 0.0f;
        }
    }
}

// ---------------- fused weight+bias repack (single launch, fp32) ------------
// R13 permutation: out row r -> h = r>>2, gate = r&3
struct PackArgs {
    const float* wsrc[8]; float* wdst[8]; int K[8]; int Kp[8];
    const float* bsrc[4]; float* bdst[4];
};
__global__ void pack_all(PackArgs pa) {
    int off[9];
    off[0] = 0;
#pragma unroll
    for (int s = 0; s < 8; s++) off[s + 1] = off[s] + H4 * pa.Kp[s];
    int totalW = off[8];
    int total = totalW + 4 * H4;
    for (int idx = blockIdx.x * blockDim.x + threadIdx.x; idx < total;
         idx += gridDim.x * blockDim.x) {
        if (idx < totalW) {
            int s = 0;
#pragma unroll
            for (int q = 0; q < 8; q++) if (idx >= off[q + 1]) s = q + 1;
            int li = idx - off[s];
            int Kp = pa.Kp[s], K = pa.K[s];
            int r = li / Kp, k = li - r * Kp;
            int h = r >> 2, g = r & 3;
            pa.wdst[s][li] = (k < K) ? pa.wsrc[s][(size_t)(g * Hh + h) * K + k] : 0.0f;
        } else {
            int li = idx - totalW;
            int s = li / H4, j = li - s * H4;
            int h = j >> 2, g = j & 3;
            pa.bdst[s][j] = pa.bsrc[s][g * Hh + h];
        }
    }
}

// ---------------- ws1 pad: 350x1024 -> 384x1024 (zeros) ----------------------
__global__ void pack_ws1b(const float* __restrict__ ws1) {
    int total = DAaP * H2;
    for (int i = blockIdx.x * blockDim.x + threadIdx.x; i < total;
         i += gridDim.x * blockDim.x) {
        int r = i / H2, k = i - r * H2;
        g_ws1p[i] = (r < DAa) ? ws1[(size_t)r * H2 + k] : 0.0f;
    }
}

// ---------------- tf32 tensor-core GEMM (3xTF32, inline split) ---------------
// C = A @ B^T ; M,N multiples of 128; K multiple of 16. fwd+bwd via blockIdx.z.
// Double-buffered smem; __launch_bounds__(256,2) caps regs at 128 -> 2 blk/SM.
__global__ __launch_bounds__(256, 2)
void gemm_tf32_2(const float* __restrict__ A,
                 const float* __restrict__ Bf, const float* __restrict__ Bb,
                 float* __restrict__ Cf, float* __restrict__ Cb,
                 int M, int N, int K, int act) {
    extern __shared__ uint32_t sm[];
    const float* Bm = blockIdx.z ? Bb : Bf;
    float* C = blockIdx.z ? Cb : Cf;

    const int tid = threadIdx.x;
    const int lane = tid & 31, warp = tid >> 5;
    const int wm = warp >> 2, wn = warp & 3;
    const int g = lane >> 2, t4 = lane & 3;
    const int m0 = blockIdx.y * 128, n0 = blockIdx.x * 128;
    const int lrow = tid >> 1;
    const int lhalf = (tid & 1) * 8;

    float acc[4][4][4];
#pragma unroll
    for (int i = 0; i < 4; i++)
#pragma unroll
        for (int j = 0; j < 4; j++)
#pragma unroll
            for (int q = 0; q < 4; q++) acc[i][j][q] = 0.0f;

    const float* Aptr = A + (size_t)(m0 + lrow) * K + lhalf;
    const float* Bptr = Bm + (size_t)(n0 + lrow) * K + lhalf;
    float4 pa0 = *(const float4*)Aptr;
    float4 pa1 = *(const float4*)(Aptr + 4);
    float4 pb0 = *(const float4*)Bptr;
    float4 pb1 = *(const float4*)(Bptr + 4);

    for (int k0 = 0; k0 < K; k0 += 16) {
        uint32_t* S = sm + ((k0 >> 4) & 1) * 10240;
        uint32_t* Ahi = S;
        uint32_t* Alo = S + 2560;
        uint32_t* Bhi = S + 5120;
        uint32_t* Blo = S + 7680;
        {
            uint4 h, l;
            tf32split(pa0.x, h.x, l.x); tf32split(pa0.y, h.y, l.y);
            tf32split(pa0.z, h.z, l.z); tf32split(pa0.w, h.w, l.w);
            *(uint4*)&Ahi[lrow * 20 + lhalf] = h; *(uint4*)&Alo[lrow * 20 + lhalf] = l;
            tf32split(pa1.x, h.x, l.x); tf32split(pa1.y, h.y, l.y);
            tf32split(pa1.z, h.z, l.z); tf32split(pa1.w, h.w, l.w);
            *(uint4*)&Ahi[lrow * 20 + lhalf + 4] = h; *(uint4*)&Alo[lrow * 20 + lhalf + 4] = l;
            tf32split(pb0.x, h.x, l.x); tf32split(pb0.y, h.y, l.y);
            tf32split(pb0.z, h.z, l.z); tf32split(pb0.w, h.w, l.w);
            *(uint4*)&Bhi[lrow * 20 + lhalf] = h; *(uint4*)&Blo[lrow * 20 + lhalf] = l;
            tf32split(pb1.x, h.x, l.x); tf32split(pb1.y, h.y, l.y);
            tf32split(pb1.z, h.z, l.z); tf32split(pb1.w, h.w, l.w);
            *(uint4*)&Bhi[lrow * 20 + lhalf + 4] = h; *(uint4*)&Blo[lrow * 20 + lhalf + 4] = l;
        }
        __syncthreads();
        int k1 = k0 + 16;
        if (k1 < K) {
            pa0 = *(const float4*)(Aptr + k1);
            pa1 = *(const float4*)(Aptr + k1 + 4);
            pb0 = *(const float4*)(Bptr + k1);
            pb1 = *(const float4*)(Bptr + k1 + 4);
        }
#pragma unroll
        for (int k8 = 0; k8 < 16; k8 += 8) {
            uint32_t bh[4][2], bl[4][2];
#pragma unroll
            for (int tn = 0; tn < 4; tn++) {
                int nr = wn * 32 + tn * 8 + g;
                bh[tn][0] = Bhi[nr * 20 + k8 + t4]; bh[tn][1] = Bhi[nr * 20 + k8 + t4 + 4];
                bl[tn][0] = Blo[nr * 20 + k8 + t4]; bl[tn][1] = Blo[nr * 20 + k8 + t4 + 4];
            }
#pragma unroll
            for (int tm = 0; tm < 4; tm++) {
                int mr = wm * 64 + tm * 16 + g;
                uint32_t ah0 = Ahi[mr * 20 + k8 + t4],       ah1 = Ahi[(mr + 8) * 20 + k8 + t4];
                uint32_t ah2 = Ahi[mr * 20 + k8 + t4 + 4],   ah3 = Ahi[(mr + 8) * 20 + k8 + t4 + 4];
                uint32_t al0 = Alo[mr * 20 + k8 + t4],       al1 = Alo[(mr + 8) * 20 + k8 + t4];
                uint32_t al2 = Alo[mr * 20 + k8 + t4 + 4],   al3 = Alo[(mr + 8) * 20 + k8 + t4 + 4];
#pragma unroll
                for (int tn = 0; tn < 4; tn++) {
                    mma_tf32(acc[tm][tn], ah0, ah1, ah2, ah3, bh[tn][0], bh[tn][1]);
                    mma_tf32(acc[tm][tn], ah0, ah1, ah2, ah3, bl[tn][0], bl[tn][1]);
                    mma_tf32(acc[tm][tn], al0, al1, al2, al3, bh[tn][0], bh[tn][1]);
                }
            }
        }
    }
#pragma unroll
    for (int tm = 0; tm < 4; tm++) {
#pragma unroll
        for (int tn = 0; tn < 4; tn++) {
            int m = m0 + wm * 64 + tm * 16 + g;
            int n = n0 + wn * 32 + tn * 8 + 2 * t4;
            float v0 = acc[tm][tn][0], v1 = acc[tm][tn][1];
            float v2 = acc[tm][tn][2], v3 = acc[tm][tn][3];
            if (act) { v0 = tanhf(v0); v1 = tanhf(v1); v2 = tanhf(v2); v3 = tanhf(v3); }
            *(float2*)&C[(size_t)m * N + n] = make_float2(v0, v1);
            *(float2*)&C[(size_t)(m + 8) * N + n] = make_float2(v2, v3);
        }
    }
}

// ---------------- fused LSTM recurrence step (R7/R13-proven FFMA2) -----------
__global__ __launch_bounds__(256)
void recur_fused(int step,
                 const float* __restrict__ Wpf, const float* __restrict__ Wpb,
                 const float* __restrict__ bpf, const float* __restrict__ bpb,
                 const float* __restrict__ pre_f, const float* __restrict__ pre_b,
                 const float* __restrict__ hinf, const float* __restrict__ hinb,
                 float* __restrict__ houtf, float* __restrict__ houtb,
                 float* __restrict__ out) {
    const int tid = threadIdx.x;
    const int tx = tid & 31, ty = tid >> 5;
    const int h0 = blockIdx.x * 32;
    const int b0 = blockIdx.y * 64;
    const int dir = blockIdx.z;
    const float* W   = dir ? Wpb : Wpf;
    const float* bia = dir ? bpb : bpf;
    const float* pre = dir ? pre_b : pre_f;
    const float* hin = dir ? hinb : hinf;
    float* hout = dir ? houtb : houtf;
    float* cs   = dir ? g_cb : g_cf;
    const int tc = dir ? (Tt - 1 - step) : step;

    __shared__ __align__(16) float Hs[16][68];
    __shared__ __align__(16) float Ws[16][132];

    ull acc[8][2];
#pragma unroll
    for (int i = 0; i < 8; i++) { acc[i][0] = 0ULL; acc[i][1] = 0ULL; }

    const float* Wbase = W + (size_t)(4 * h0) * Hh;
    const int lr = tid >> 2;
    const int lk = (tid & 3) << 2;

    float4 ph  = *(const float4*)&hin[(b0 + lr) * Hh + lk];
    float4 pw0 = *(const float4*)&Wbase[(size_t)lr * Hh + lk];
    float4 pw1 = *(const float4*)&Wbase[(size_t)(lr + 64) * Hh + lk];

    for (int k0 = 0; k0 < Hh; k0 += 16) {
        __syncthreads();
        Hs[lk + 0][lr] = ph.x; Hs[lk + 1][lr] = ph.y;
        Hs[lk + 2][lr] = ph.z; Hs[lk + 3][lr] = ph.w;
        Ws[lk + 0][lr] = pw0.x; Ws[lk + 1][lr] = pw0.y;
        Ws[lk + 2][lr] = pw0.z; Ws[lk + 3][lr] = pw0.w;
        Ws[lk + 0][lr + 64] = pw1.x; Ws[lk + 1][lr + 64] = pw1.y;
        Ws[lk + 2][lr + 64] = pw1.z; Ws[lk + 3][lr + 64] = pw1.w;
        __syncthreads();
        int k1 = k0 + 16;
        if (k1 < Hh) {
            ph  = *(const float4*)&hin[(b0 + lr) * Hh + k1 + lk];
            pw0 = *(const float4*)&Wbase[(size_t)lr * Hh + k1 + lk];
            pw1 = *(const float4*)&Wbase[(size_t)(lr + 64) * Hh + k1 + lk];
        }
#pragma unroll
        for (int k = 0; k < 16; k++) {
            ull b2[2];
            const ull* bp2 = (const ull*)&Ws[k][tx << 2];
            b2[0] = bp2[0]; b2[1] = bp2[1];
#pragma unroll
            for (int i = 0; i < 8; i++) {
                float a = Hs[k][(ty << 3) + i];
                ull ad = pack2(a, a);
                acc[i][0] = ffma2(ad, b2[0], acc[i][0]);
                acc[i][1] = ffma2(ad, b2[1], acc[i][1]);
            }
        }
    }

    const int h = h0 + tx;
    const float4 b4 = *(const float4*)&bia[4 * h];
#pragma unroll
    for (int i = 0; i < 8; i++) {
        int b = b0 + (ty << 3) + i;
        float zi, zf_, zg, zo;
        unpack2(acc[i][0], zi, zf_);
        unpack2(acc[i][1], zg, zo);
        float4 pr = *(const float4*)&pre[((size_t)tc * Bq + b) * H4 + 4 * h];
        zi += pr.x + b4.x; zf_ += pr.y + b4.y;
        zg += pr.z + b4.z; zo += pr.w + b4.w;
        float c = cs[b * Hh + h];
        c = sigf(zf_) * c + sigf(zi) * tanhf(zg);
        float hn = sigf(zo) * tanhf(c);
        cs[b * Hh + h] = c;
        hout[b * Hh + h] = hn;
        out[((size_t)tc * Bq + b) * H2 + dir * Hh + h] = hn;
    }
}

// ---------------- zero LSTM states ------------------------------------------
__global__ void zero_states_kernel() {
    int i = blockIdx.x * blockDim.x + threadIdx.x;
    if (i < Bq * Hh) {
        g_hf2[0][i] = 0.0f; g_hf2[1][i] = 0.0f;
        g_hb2[0][i] = 0.0f; g_hb2[1][i] = 0.0f;
        g_cf[i] = 0.0f; g_cb[i] = 0.0f;
    }
}

// ---------------- alphas: [tb][r] = dot(hbar[tb], ws2[r]) -------------------
__global__ void alphas_kernel(const float* __restrict__ hbar,
                              const float* __restrict__ ws2,
                              float* __restrict__ alph) {
    __shared__ float w[Rr * 353];
    int tid = threadIdx.x;  // 128
    for (int i = tid; i < Rr * DAa; i += 128) {
        int r = i / DAa, k = i - r * DAa;
        w[r * 353 + k] = ws2[i];
    }
    __syncthreads();
    int row = blockIdx.x * 8 + (tid >> 4);
    int r = tid & 15;
    const float* hb = hbar + (size_t)row * DAaP;
    float acc = 0.0f;
    for (int k = 0; k < DAa; k++) acc += hb[k] * w[r * 353 + k];
    alph[(size_t)row * Rr + r] = acc;
}

// ---------------- sent: sent[b,r,e] = sum_t alphas[t,b,r] * l1[t,b,e] -------
__global__ void sent_kernel(const float* __restrict__ alphas,
                            const float* __restrict__ l1,
                            float* __restrict__ outSent) {
    int b = blockIdx.x;
    __shared__ float al[Tt * Rr];
    int tid = threadIdx.x;
    for (int i = tid; i < Tt * Rr; i += 256) {
        int t = i / Rr, r = i % Rr;
        al[i] = alphas[(size_t)(t * Bq + b) * Rr + r];
    }
    __syncthreads();
    for (int e = tid; e < H2; e += 256) {
        float acc[Rr];
#pragma unroll
        for (int r = 0; r < Rr; r++) acc[r] = 0.0f;
        for (int t = 0; t < Tt; t++) {
            float v = l1[(size_t)(t * Bq + b) * H2 + e];
#pragma unroll
            for (int r = 0; r < Rr; r++) acc[r] += al[t * Rr + r] * v;
        }
#pragma unroll
        for (int r = 0; r < Rr; r++)
            outSent[(size_t)(b * Rr + r) * H2 + e] = acc[r];
    }
}

// ---------------- votes: per-r NN GEMM, f32x2, gemm128 pattern (R12 WIN) -----
__global__ __launch_bounds__(256)
void votes_f32x2(const float* __restrict__ sent, const float* __restrict__ capsW,
                 float* __restrict__ votes) {
    const int rr = blockIdx.z;
    const float* Bp = capsW + (size_t)rr * H2 * (Ss * Aa);
    __shared__ __align__(16) float As[16][132];
    __shared__ __align__(16) float Bs[16][132];
    const int tid = threadIdx.x;
    const int tx = tid & 15, ty = tid >> 4;
    const int m0 = blockIdx.y * 128, n0 = blockIdx.x * 128;
    const int lr = tid >> 2;
    const int lk = (tid & 3) << 2;

    ull acc[8][4];
#pragma unroll
    for (int i = 0; i < 8; i++)
#pragma unroll
        for (int j = 0; j < 4; j++) acc[i][j] = 0ULL;

    float4 pa0 = *(const float4*)&sent[((size_t)(m0 + lr) * Rr + rr) * H2 + lk];
    float4 pa1 = *(const float4*)&sent[((size_t)(m0 + lr + 64) * Rr + rr) * H2 + lk];
    const int kr = tid >> 5;
    const int nc = (tid & 31) << 2;
    float4 pb0 = *(const float4*)&Bp[(size_t)(kr)     * (Ss * Aa) + n0 + nc];
    float4 pb1 = *(const float4*)&Bp[(size_t)(kr + 8) * (Ss * Aa) + n0 + nc];

    for (int k0 = 0; k0 < H2; k0 += 16) {
        __syncthreads();
        As[lk + 0][lr] = pa0.x; As[lk + 1][lr] = pa0.y;
        As[lk + 2][lr] = pa0.z; As[lk + 3][lr] = pa0.w;
        As[lk + 0][lr + 64] = pa1.x; As[lk + 1][lr + 64] = pa1.y;
        As[lk + 2][lr + 64] = pa1.z; As[lk + 3][lr + 64] = pa1.w;
        *(float4*)&Bs[kr][nc]     = pb0;
        *(float4*)&Bs[kr + 8][nc] = pb1;
        __syncthreads();
        int k1 = k0 + 16;
        if (k1 < H2) {
            pa0 = *(const float4*)&sent[((size_t)(m0 + lr) * Rr + rr) * H2 + k1 + lk];
            pa1 = *(const float4*)&sent[((size_t)(m0 + lr + 64) * Rr + rr) * H2 + k1 + lk];
            pb0 = *(const float4*)&Bp[(size_t)(k1 + kr)     * (Ss * Aa) + n0 + nc];
            pb1 = *(const float4*)&Bp[(size_t)(k1 + kr + 8) * (Ss * Aa) + n0 + nc];
        }
#pragma unroll
        for (int k = 0; k < 16; k++) {
            ull b2[4];
            const ull* bp = (const ull*)&Bs[k][tx << 3];
            b2[0] = bp[0]; b2[1] = bp[1]; b2[2] = bp[2]; b2[3] = bp[3];
#pragma unroll
            for (int i = 0; i < 8; i++) {
                float a = As[k][(ty << 3) + i];
                ull ad = pack2(a, a);
#pragma unroll
                for (int j = 0; j < 4; j++) acc[i][j] = ffma2(ad, b2[j], acc[i][j]);
            }
        }
    }
#pragma unroll
    for (int i = 0; i < 8; i++) {
        int m = m0 + (ty << 3) + i;
#pragma unroll
        for (int j = 0; j < 4; j++) {
            float lo, hi;
            unpack2(acc[i][j], lo, hi);
            int n = n0 + (tx << 3) + 2 * j;
            votes[((size_t)m * Rr + rr) * (Ss * Aa) + n]     = lo;
            votes[((size_t)m * Rr + rr) * (Ss * Aa) + n + 1] = hi;
        }
    }
}

// ---------------- dynamic routing (NR=3) + class logits ---------------------
__global__ void routing_kernel(const float* __restrict__ votes,
                               float* __restrict__ outCls) {
    int b = blockIdx.x, tid = threadIdx.x;
    __shared__ float logits[Rr * Ss];
    __shared__ float route[Rr * Ss];
    __shared__ float pre[Ss * Aa];
    __shared__ float scale[Ss];
    for (int i = tid; i < Rr * Ss; i += 256) logits[i] = 0.0f;
    const float* vb = votes + (size_t)b * Rr * Ss * Aa;
    for (int it = 0; it < NRr; it++) {
        __syncthreads();
        if (tid < Rr) {
            float mx = -1e30f;
            for (int s = 0; s < Ss; s++) mx = fmaxf(mx, logits[tid * Ss + s]);
            float sum = 0.0f;
            for (int s = 0; s < Ss; s++) {
                float e = expf(logits[tid * Ss + s] - mx);
                route[tid * Ss + s] = e;
                sum += e;
            }
            float inv = 1.0f / sum;
            for (int s = 0; s < Ss; s++) route[tid * Ss + s] *= inv;
        }
        __syncthreads();
        for (int i = tid; i < Ss * Aa; i += 256) {
            int s = i / Aa, a = i % Aa;
            float acc = 0.0f;
            for (int r = 0; r < Rr; r++)
                acc += route[r * Ss + s] * vb[(r * Ss + s) * Aa + a];
            pre[i] = acc;
        }
        __syncthreads();
        if (tid < Ss) {
            float n2 = 0.0f;
            for (int a = 0; a < Aa; a++) n2 += pre[tid * Aa + a] * pre[tid * Aa + a];
            float n = sqrtf(n2);
            scale[tid] = n / (0.5f + n2);
            if (it == NRr - 1) outCls[b * Ss + tid] = n2 / (0.5f + n2);
        }
        __syncthreads();
        if (it < NRr - 1) {
            for (int i = tid; i < Rr * Ss; i += 256) {
                int r = i / Ss, s = i % Ss;
                float acc = 0.0f;
                float sc = scale[s];
                for (int a = 0; a < Aa; a++)
                    acc += vb[(r * Ss + s) * Aa + a] * pre[s * Aa + a] * sc;
                logits[i] += acc;
            }
        }
    }
}

// ---------------- host launch ------------------------------------------------
static float* symf(const void* s) {
    void* p = nullptr;
    cudaGetSymbolAddress(&p, s);
    return (float*)p;
}

extern "C" void kernel_launch(void* const* d_in, const int* in_sizes, int n_in,
                              void* d_out, int out_size) {
    const int*   tokens  = (const int*)d_in[0];
    const float* emb     = (const float*)d_in[2];
    const float* Wih_l0f = (const float*)d_in[3];
    const float* Whh_l0f = (const float*)d_in[4];
    const float* b_l0f   = (const float*)d_in[5];
    const float* Wih_l0b = (const float*)d_in[6];
    const float* Whh_l0b = (const float*)d_in[7];
    const float* b_l0b   = (const float*)d_in[8];
    const float* Wih_l1f = (const float*)d_in[9];
    const float* Whh_l1f = (const float*)d_in[10];
    const float* b_l1f   = (const float*)d_in[11];
    const float* Wih_l1b = (const float*)d_in[12];
    const float* Whh_l1b = (const float*)d_in[13];
    const float* b_l1b   = (const float*)d_in[14];
    const float* ws1     = (const float*)d_in[15];
    const float* ws2     = (const float*)d_in[16];
    const float* capsW   = (const float*)d_in[17];
    float* out = (float*)d_out;

    float* x     = symf(g_x);
    float* pre_f = symf(g_pre_f);
    float* pre_b = symf(g_pre_b);
    float* l0    = symf(g_l0);
    float* l1    = symf(g_l1);
    float* hbar  = symf(g_hbar);
    float* alph  = symf(g_alphas);
    float* votes = symf(g_votes);
    float* ws1p  = symf(g_ws1p);
    float* wih0f = symf(g_wih0f); float* wih0b = symf(g_wih0b);
    float* wih1f = symf(g_wih1f); float* wih1b = symf(g_wih1b);
    float* whh0f = symf(g_whh0f); float* whh0b = symf(g_whh0b);
    float* whh1f = symf(g_whh1f); float* whh1b = symf(g_whh1b);
    float* bp0f  = symf(g_b0f);   float* bp0b  = symf(g_b0b);
    float* bp1f  = symf(g_b1f);   float* bp1b  = symf(g_b1b);
    float* hfbase = symf(g_hf2);
    float* hbbase = symf(g_hb2);
    float* hf0 = hfbase;              float* hf1 = hfbase + Bq * Hh;
    float* hb0 = hbbase;              float* hb1 = hbbase + Bq * Hh;

    const int MB = Tt * Bq;  // 16384
    const int GT_SMEM = 81920;  // 2-stage double buffer

    cudaFuncSetAttribute(gemm_tf32_2, cudaFuncAttributeMaxDynamicSharedMemorySize, GT_SMEM);

    // 1. embedding (padded) + fused weight/bias repack + ws1 pad
    embed_kernel<<<4096, 256>>>(tokens, emb);
    {
        PackArgs pa;
        pa.wsrc[0] = Wih_l0f; pa.wdst[0] = wih0f; pa.K[0] = Ee;  pa.Kp[0] = EeP;
        pa.wsrc[1] = Wih_l0b; pa.wdst[1] = wih0b; pa.K[1] = Ee;  pa.Kp[1] = EeP;
        pa.wsrc[2] = Wih_l1f; pa.wdst[2] = wih1f; pa.K[2] = H2;  pa.Kp[2] = H2;
        pa.wsrc[3] = Wih_l1b; pa.wdst[3] = wih1b; pa.K[3] = H2;  pa.Kp[3] = H2;
        pa.wsrc[4] = Whh_l0f; pa.wdst[4] = whh0f; pa.K[4] = Hh;  pa.Kp[4] = Hh;
        pa.wsrc[5] = Whh_l0b; pa.wdst[5] = whh0b; pa.K[5] = Hh;  pa.Kp[5] = Hh;
        pa.wsrc[6] = Whh_l1f; pa.wdst[6] = whh1f; pa.K[6] = Hh;  pa.Kp[6] = Hh;
        pa.wsrc[7] = Whh_l1b; pa.wdst[7] = whh1b; pa.K[7] = Hh;  pa.Kp[7] = Hh;
        pa.bsrc[0] = b_l0f; pa.bdst[0] = bp0f;
        pa.bsrc[1] = b_l0b; pa.bdst[1] = bp0b;
        pa.bsrc[2] = b_l1f; pa.bdst[2] = bp1f;
        pa.bsrc[3] = b_l1b; pa.bdst[3] = bp1b;
        pack_all<<<4096, 256>>>(pa);
    }
    pack_ws1b<<<1536, 256>>>(ws1);

    dim3 gP(H4 / 128, MB / 128, 2);  // projections fwd+bwd in one launch
    dim3 gR(Hh / 32, Bq / 64, 2);    // recurrence: 16 x 4 x 2

    // 2. layer0 input projections (tf32 tensor cores, 3xTF32, double-buffered)
    gemm_tf32_2<<<gP, 256, GT_SMEM>>>(x, wih0f, wih0b, pre_f, pre_b, MB, H4, EeP, 0);

    // 3. layer0 recurrence (per-step, h ping-pong)
    zero_states_kernel<<<(Bq * Hh + 255) / 256, 256>>>();
    for (int t = 0; t < Tt; t++) {
        float* hinf = (t & 1) ? hf1 : hf0;  float* houtf = (t & 1) ? hf0 : hf1;
        float* hinb = (t & 1) ? hb1 : hb0;  float* houtb = (t & 1) ? hb0 : hb1;
        recur_fused<<<gR, 256>>>(t, whh0f, whh0b, bp0f, bp0b, pre_f, pre_b,
                                 hinf, hinb, houtf, houtb, l0);
    }

    // 4. layer1 input projections
    gemm_tf32_2<<<gP, 256, GT_SMEM>>>(l0, wih1f, wih1b, pre_f, pre_b, MB, H4, H2, 0);

    // 5. layer1 recurrence
    zero_states_kernel<<<(Bq * Hh + 255) / 256, 256>>>();
    for (int t = 0; t < Tt; t++) {
        float* hinf = (t & 1) ? hf1 : hf0;  float* houtf = (t & 1) ? hf0 : hf1;
        float* hinb = (t & 1) ? hb1 : hb0;  float* houtb = (t & 1) ? hb0 : hb1;
        recur_fused<<<gR, 256>>>(t, whh1f, whh1b, bp1f, bp1b, pre_f, pre_b,
                                 hinf, hinb, houtf, houtb, l1);
    }

    // 6. attention: hbar = tanh(l1 @ ws1p^T) via tf32 (N padded to 384)
    gemm_tf32_2<<<dim3(DAaP / 128, MB / 128, 1), 256, GT_SMEM>>>(
        l1, ws1p, ws1p, hbar, hbar, MB, DAaP, H2, 1);
    alphas_kernel<<<MB / 8, 128>>>(hbar, ws2, alph);

    // 7. sent -> d_out[0 : B*R*2H)
    sent_kernel<<<Bq, 256>>>(alph, l1, out);

    // 8. votes (f32x2, gemm128 pattern)
    votes_f32x2<<<dim3((Ss * Aa) / 128, Bq / 128, Rr), 256>>>(out, capsW, votes);

    // 9. routing -> class logits
    routing_kernel<<<Bq, 256>>>(votes, out + (size_t)Bq * Rr * H2);
}